// round 12
// baseline (speedup 1.0000x reference)
#include <cuda_runtime.h>
#include <math.h>
#include <stdint.h>

#define NTOK 32768
#define NM   4
#define IND  204
#define HD   128
#define AD   14
#define KD   32
#define TT   32
#define NTHR 256
#define FULL 0xffffffffu

#define PITCH   264
#define XPITCH  212
#define HPITCH  132
#define OFF_XP  8448
#define OFF_TOK 15232
#define SMEM_BYTES ((OFF_TOK + 40) * 4)

// ---------------- device scratch ----------------
__device__ float    g_kp[NM * KD];
__device__ int      g_cnt[NM];
__device__ int      g_ticket;
__device__ int      g_idx[NM * NTOK];
// B-fragment-packed tf32 weight images: [kb][n][8] with (k,k+4) pairs adjacent
__device__ __align__(128) uint32_t g_bf1[NM * 26 * 128 * 8];   // fc1: K=208(pad), N=128
__device__ __align__(128) uint32_t g_brz[NM * 32 * 256 * 8];   // r|z: K=256 ([Wi;Wh]), N=256
__device__ __align__(128) uint32_t g_bnq[NM * 16 * 256 * 8];   // inn|hn: K=128, N=256

__device__ __forceinline__ float sigmf(float v) { return 1.0f / (1.0f + __expf(-v)); }
__device__ __forceinline__ uint32_t f2tf(float f) {
    uint32_t r; asm("cvt.rna.tf32.f32 %0,%1;" : "=r"(r) : "f"(f)); return r;
}
__device__ __forceinline__ void mma8(float c[4], const uint32_t a[4], uint2 b) {
    asm volatile("mma.sync.aligned.m16n8k8.row.col.f32.tf32.tf32.f32 "
                 "{%0,%1,%2,%3},{%4,%5,%6,%7},{%8,%9},{%0,%1,%2,%3};"
                 : "+f"(c[0]), "+f"(c[1]), "+f"(c[2]), "+f"(c[3])
                 : "r"(a[0]), "r"(a[1]), "r"(a[2]), "r"(a[3]), "r"(b.x), "r"(b.y));
}
// pair-interleave offset of column k within a row (A-fragment layout)
__device__ __forceinline__ int pil(int k) {
    return ((k >> 3) << 3) + ((k & 3) << 1) + ((k & 7) >> 2);
}

// ---------------- kernel 0: keys + resets ----------------
__global__ void kp_kernel(const float* __restrict__ mech_keys,
                          const float* __restrict__ wk,
                          const float* __restrict__ bk)
{
    int tid = threadIdx.x;
    if (tid == 0) g_ticket = 0;
    if (tid < NM) g_cnt[tid] = 0;
    if (tid < NM * KD) {
        int m = tid >> 5, k = tid & 31;
        float acc = bk[k];
        #pragma unroll
        for (int i = 0; i < KD; i++)
            acc = fmaf(mech_keys[m * KD + i], wk[i * KD + k], acc);
        g_kp[tid] = acc;
    }
}

// ---------------- prep: pack weights into B-fragment tf32 images ----------------
#define NBF1 (NM * 26 * 128 * 8)
#define NBRZ (NM * 32 * 256 * 8)
#define NBNQ (NM * 16 * 256 * 8)
__global__ void prep_kernel(const float* __restrict__ fc1w,
                            const float* __restrict__ wih,
                            const float* __restrict__ whh)
{
    int e = blockIdx.x * blockDim.x + threadIdx.x;
    if (e < NBF1) {
        int m = e / 26624, r = e % 26624;
        int kb = r / 1024, r2 = r % 1024;
        int n = r2 >> 3, p = r2 & 7;
        int k = kb * 8 + (p >> 1) + ((p & 1) << 2);
        float v = (k < IND) ? fc1w[((size_t)m * IND + k) * HD + n] : 0.0f;
        g_bf1[e] = f2tf(v);
    } else if (e < NBF1 + NBRZ) {
        int e2 = e - NBF1;
        int m = e2 / 65536, r = e2 % 65536;
        int kb = r / 2048, r2 = r % 2048;
        int n = r2 >> 3, p = r2 & 7;
        int k = kb * 8 + (p >> 1) + ((p & 1) << 2);
        int gate = n >> 7, col = n & 127;
        float v = (k < 128) ? wih[((size_t)m * HD + k) * 384 + gate * 128 + col]
                            : whh[((size_t)m * HD + (k - 128)) * 384 + gate * 128 + col];
        g_brz[e2] = f2tf(v);
    } else if (e < NBF1 + NBRZ + NBNQ) {
        int e3 = e - NBF1 - NBRZ;
        int m = e3 / 32768, r = e3 % 32768;
        int kb = r / 2048, r2 = r % 2048;
        int n = r2 >> 3, p = r2 & 7;
        int k = kb * 8 + (p >> 1) + ((p & 1) << 2);
        int sel = n >> 7, col = n & 127;
        float v = (sel == 0) ? wih[((size_t)m * HD + k) * 384 + 256 + col]
                             : whh[((size_t)m * HD + k) * 384 + 256 + col];
        g_bnq[e3] = f2tf(v);
    }
}

// ---------------- router (proven fp32 path, unchanged) ----------------
__device__ __forceinline__ void layer32(const float* __restrict__ W,
                                        const float* __restrict__ B,
                                        float cur[8], int l, int do_relu)
{
    float nxt[8];
    #pragma unroll
    for (int t = 0; t < 8; t++) nxt[t] = B[l];
    #pragma unroll 4
    for (int i = 0; i < KD; i++) {
        float wv = W[i * KD + l];
        #pragma unroll
        for (int t = 0; t < 8; t++)
            nxt[t] = fmaf(__shfl_sync(FULL, cur[t], i), wv, nxt[t]);
    }
    #pragma unroll
    for (int t = 0; t < 8; t++)
        cur[t] = do_relu ? fmaxf(nxt[t], 0.0f) : nxt[t];
}

__global__ __launch_bounds__(256) void router_kernel(
    const float* __restrict__ hid,
    const float* __restrict__ w1, const float* __restrict__ b1,
    const float* __restrict__ w2, const float* __restrict__ b2,
    const float* __restrict__ w3, const float* __restrict__ b3,
    const float* __restrict__ wq, const float* __restrict__ bq,
    const float* __restrict__ unif)
{
    __shared__ float hs[64 * HD];
    const int tid = threadIdx.x;
    const int t0 = blockIdx.x * 64;
    {
        const float4* src = (const float4*)(hid + (size_t)t0 * HD);
        float4* dst = (float4*)hs;
        for (int e = tid; e < 64 * HD / 4; e += 256) dst[e] = src[e];
    }
    __syncthreads();
    const int w = tid >> 5, l = tid & 31;
    const int wt0 = w * 8;
    float cur[8];
    #pragma unroll
    for (int t = 0; t < 8; t++) cur[t] = b1[l];
    #pragma unroll 4
    for (int i = 0; i < HD; i++) {
        float wv = w1[i * KD + l];
        #pragma unroll
        for (int t = 0; t < 8; t++)
            cur[t] = fmaf(hs[(wt0 + t) * HD + i], wv, cur[t]);
    }
    #pragma unroll
    for (int t = 0; t < 8; t++) cur[t] = fmaxf(cur[t], 0.0f);
    layer32(w2, b2, cur, l, 1);
    layer32(w3, b3, cur, l, 0);
    layer32(wq, bq, cur, l, 0);

    const float scale = 0.17677669529663687f;
    int mysel = 0;
    int mytok = t0 + wt0 + l;
    #pragma unroll
    for (int t = 0; t < 8; t++) {
        float lg[NM];
        #pragma unroll
        for (int m = 0; m < NM; m++) {
            float p = cur[t] * g_kp[m * KD + l];
            #pragma unroll
            for (int off = 16; off > 0; off >>= 1)
                p += __shfl_xor_sync(FULL, p, off);
            lg[m] = p * scale;
        }
        float mx = fmaxf(fmaxf(lg[0], lg[1]), fmaxf(lg[2], lg[3]));
        float es[NM]; float ssum = 0.0f;
        #pragma unroll
        for (int m = 0; m < NM; m++) { es[m] = expf(lg[m] - mx); ssum += es[m]; }
        float inv = 1.0f / ssum;
        int gt = t0 + wt0 + t;
        float best = -1e30f; int sel = 0;
        #pragma unroll
        for (int m = 0; m < NM; m++) {
            float u = unif[gt * NM + m];
            float gmb = -logf(-logf(u + 1e-10f) + 1e-10f);
            float y = es[m] * inv + gmb;
            if (y > best) { best = y; sel = m; }
        }
        if (l == t) mysel = sel;
    }
    #pragma unroll
    for (int m = 0; m < NM; m++) {
        unsigned mask = __ballot_sync(FULL, (l < 8) && (mysel == m));
        if (mask) {
            int leader = __ffs(mask) - 1;
            int base = 0;
            if (l == leader) base = atomicAdd(&g_cnt[m], __popc(mask));
            base = __shfl_sync(FULL, base, leader);
            if ((l < 8) && (mysel == m)) {
                int pos = base + __popc(mask & ((1u << l) - 1));
                g_idx[m * NTOK + pos] = mytok;
            }
        }
    }
}

// ---------------- mech: persistent mma.sync-tf32 fused GRU agent, tf32-in-smem ----------------
__global__ __launch_bounds__(NTHR, 2) void mech_kernel(
    const float* __restrict__ x, const float* __restrict__ hid,
    const float* __restrict__ fc1b,
    const float* __restrict__ bih, const float* __restrict__ bhh,
    const float* __restrict__ fc2w, const float* __restrict__ fc2b,
    float* __restrict__ out)
{
    extern __shared__ float sm[];
    uint32_t* Gp = (uint32_t*)sm;       // [32][264] tf32 pair-interleaved: 0-127 XA, 128-255 H
    uint32_t* Xp = (uint32_t*)(sm + OFF_XP); // [32][212] tf32 pair-interleaved X (dead after fc1)
    float* HN = sm + OFF_XP;            // [32][132] plain fp32 hnew (aliases Xp)
    int* toks = (int*)(sm + OFF_TOK);
    int* s_tk = toks + TT;

    const int tid = threadIdx.x;
    const int w = tid >> 5, l = tid & 31;
    const int gr = l >> 2, gc = l & 3;
    const int mb = w >> 2, ng = w & 3;     // warp: m16-stripe, n32-group
    float* outH = out + (size_t)NTOK * AD;

    int cc[NM], pre[NM]; int total = 0;
    #pragma unroll
    for (int m = 0; m < NM; m++) {
        cc[m] = g_cnt[m];
        total += (cc[m] + TT - 1) / TT;
        pre[m] = total;
    }

    for (;;) {
        if (tid == 0) *s_tk = atomicAdd(&g_ticket, 1);
        __syncthreads();
        const int tk = *s_tk;
        if (tk >= total) break;
        int m = 0;
        #pragma unroll
        for (int j = 0; j < NM - 1; j++) if (tk >= pre[j]) m = j + 1;
        const int prev = m ? pre[m - 1] : 0;
        const int t0 = (tk - prev) * TT;
        const int nt_tok = min(TT, cc[m] - t0);
        if (tid < TT) toks[tid] = g_idx[m * NTOK + t0 + min(tid, nt_tok - 1)];
        __syncthreads();

        // ---- stage X as tf32 pair-interleaved into Xp ----
        for (int e = tid; e < TT * 52; e += NTHR) {
            int r = e / 52, c4 = e % 52;
            float4 v = make_float4(0.f, 0.f, 0.f, 0.f);
            if (c4 < 51) v = ((const float4*)(x + (size_t)toks[r] * IND))[c4];
            int k0 = c4 * 4;
            uint32_t* dst = Xp + r * XPITCH + ((k0 >> 3) << 3) + ((k0 & 7) >> 2);
            dst[0] = f2tf(v.x); dst[2] = f2tf(v.y); dst[4] = f2tf(v.z); dst[6] = f2tf(v.w);
        }
        // ---- stage H as tf32 pair-interleaved into Gp cols 128.. ----
        for (int e = tid; e < TT * 32; e += NTHR) {
            int r = e >> 5, c4 = e & 31;
            float4 v = ((const float4*)(hid + (size_t)toks[r] * HD))[c4];
            int k0 = 128 + c4 * 4;
            uint32_t* dst = Gp + r * PITCH + ((k0 >> 3) << 3) + ((k0 & 7) >> 2);
            dst[0] = f2tf(v.x); dst[2] = f2tf(v.y); dst[4] = f2tf(v.z); dst[6] = f2tf(v.w);
        }
        __syncthreads();

        // ---- fc1: 8 warps, warp = m16 x n32 (band = mb, ng) ----
        {
            float c[4][4];
            #pragma unroll
            for (int nt = 0; nt < 4; nt++) {
                int col = ng * 32 + nt * 8 + gc * 2;
                float b0 = __ldg(fc1b + m * HD + col);
                float b1 = __ldg(fc1b + m * HD + col + 1);
                c[nt][0] = b0; c[nt][1] = b1;
                c[nt][2] = b0; c[nt][3] = b1;
            }
            const uint32_t* Bb = g_bf1 + m * 26624;
            #pragma unroll 2
            for (int kb = 0; kb < 26; kb++) {
                uint32_t a[4];
                {
                    int row = mb * 16 + gr;
                    uint2 lo = *(const uint2*)(Xp + row * XPITCH + kb * 8 + gc * 2);
                    uint2 hi = *(const uint2*)(Xp + (row + 8) * XPITCH + kb * 8 + gc * 2);
                    a[0] = lo.x; a[1] = hi.x; a[2] = lo.y; a[3] = hi.y;
                }
                #pragma unroll
                for (int nt = 0; nt < 4; nt++) {
                    uint2 b = __ldg((const uint2*)(Bb + ((size_t)kb * 128 + ng * 32 + nt * 8 + gr) * 8 + gc * 2));
                    mma8(c[nt], a, b);
                }
            }
            // relu + tf32 + write XA pair-interleaved into Gp cols 0-127
            #pragma unroll
            for (int nt = 0; nt < 4; nt++) {
                int row = mb * 16 + gr;
                int col = ng * 32 + nt * 8 + gc * 2;
                int p = pil(col);
                Gp[row * PITCH + p]           = f2tf(fmaxf(c[nt][0], 0.f));
                Gp[row * PITCH + p + 2]       = f2tf(fmaxf(c[nt][1], 0.f));
                Gp[(row + 8) * PITCH + p]     = f2tf(fmaxf(c[nt][2], 0.f));
                Gp[(row + 8) * PITCH + p + 2] = f2tf(fmaxf(c[nt][3], 0.f));
            }
        }
        __syncthreads();

        // ---- gates (merged A-passes) + in-register GRU epilogue: warp = m16 x n32 ----
        {
            const int rowb = mb * 16;
            const uint32_t* Brz = g_brz + m * 65536;
            const uint32_t* Bnq = g_bnq + m * 32768;
            float cr[4][4], cz[4][4], cn[4][4], cq[4][4];
            #pragma unroll
            for (int nt = 0; nt < 4; nt++) {
                int col = ng * 32 + nt * 8 + gc * 2;
                float r0 = __ldg(bih + m * 384 + col) + __ldg(bhh + m * 384 + col);
                float r1 = __ldg(bih + m * 384 + col + 1) + __ldg(bhh + m * 384 + col + 1);
                float z0 = __ldg(bih + m * 384 + 128 + col) + __ldg(bhh + m * 384 + 128 + col);
                float z1 = __ldg(bih + m * 384 + 128 + col + 1) + __ldg(bhh + m * 384 + 128 + col + 1);
                float n0 = __ldg(bih + m * 384 + 256 + col);
                float n1 = __ldg(bih + m * 384 + 256 + col + 1);
                float q0 = __ldg(bhh + m * 384 + 256 + col);
                float q1 = __ldg(bhh + m * 384 + 256 + col + 1);
                cr[nt][0] = r0; cr[nt][1] = r1; cr[nt][2] = r0; cr[nt][3] = r1;
                cz[nt][0] = z0; cz[nt][1] = z1; cz[nt][2] = z0; cz[nt][3] = z1;
                cn[nt][0] = n0; cn[nt][1] = n1; cn[nt][2] = n0; cn[nt][3] = n1;
                cq[nt][0] = q0; cq[nt][1] = q1; cq[nt][2] = q0; cq[nt][3] = q1;
            }
            // pass 1: kb 0..15 (XA half) -> r, z, inn share the A fragment
            #pragma unroll 2
            for (int kb = 0; kb < 16; kb++) {
                uint32_t a[4];
                uint2 lo = *(const uint2*)(Gp + (rowb + gr) * PITCH + kb * 8 + gc * 2);
                uint2 hi = *(const uint2*)(Gp + (rowb + gr + 8) * PITCH + kb * 8 + gc * 2);
                a[0] = lo.x; a[1] = hi.x; a[2] = lo.y; a[3] = hi.y;
                #pragma unroll
                for (int nt = 0; nt < 4; nt++) {
                    int nb = ng * 32 + nt * 8 + gr;
                    uint2 br = __ldg((const uint2*)(Brz + ((size_t)kb * 256 + nb) * 8 + gc * 2));
                    uint2 bz = __ldg((const uint2*)(Brz + ((size_t)kb * 256 + 128 + nb) * 8 + gc * 2));
                    uint2 bn = __ldg((const uint2*)(Bnq + ((size_t)kb * 256 + nb) * 8 + gc * 2));
                    mma8(cr[nt], a, br);
                    mma8(cz[nt], a, bz);
                    mma8(cn[nt], a, bn);
                }
            }
            // pass 2: kb 16..31 (H half) -> r, z, hn share the A fragment
            #pragma unroll 2
            for (int kb = 16; kb < 32; kb++) {
                uint32_t a[4];
                uint2 lo = *(const uint2*)(Gp + (rowb + gr) * PITCH + kb * 8 + gc * 2);
                uint2 hi = *(const uint2*)(Gp + (rowb + gr + 8) * PITCH + kb * 8 + gc * 2);
                a[0] = lo.x; a[1] = hi.x; a[2] = lo.y; a[3] = hi.y;
                #pragma unroll
                for (int nt = 0; nt < 4; nt++) {
                    int nb = ng * 32 + nt * 8 + gr;
                    uint2 br = __ldg((const uint2*)(Brz + ((size_t)kb * 256 + nb) * 8 + gc * 2));
                    uint2 bz = __ldg((const uint2*)(Brz + ((size_t)kb * 256 + 128 + nb) * 8 + gc * 2));
                    uint2 bq = __ldg((const uint2*)(Bnq + ((size_t)(kb - 16) * 256 + 128 + nb) * 8 + gc * 2));
                    mma8(cr[nt], a, br);
                    mma8(cz[nt], a, bz);
                    mma8(cq[nt], a, bq);
                }
            }
            // in-register GRU epilogue (h from global fp32 — same value as staged)
            #pragma unroll
            for (int nt = 0; nt < 4; nt++) {
                int colb = ng * 32 + nt * 8 + gc * 2;
                #pragma unroll
                for (int idx = 0; idx < 4; idx++) {
                    int row = rowb + gr + ((idx >> 1) << 3);
                    int col = colb + (idx & 1);
                    float rv = sigmf(cr[nt][idx]);
                    float zv = sigmf(cz[nt][idx]);
                    float gg = tanhf(cn[nt][idx] + rv * cq[nt][idx]);
                    float hv = __ldg(hid + (size_t)toks[row] * HD + col);
                    float h2 = (1.0f - zv) * gg + zv * hv;
                    HN[row * HPITCH + col] = h2;
                    outH[(size_t)toks[row] * HD + col] = h2;
                }
            }
        }
        __syncthreads();

        // ---- fc2 over hnew (HN plain fp32) ----
        for (int oi = tid; oi < TT * AD; oi += NTHR) {
            int t = oi / AD, a = oi - t * AD;
            float acc = fc2b[m * AD + a];
            const float* wp = fc2w + m * HD * AD + a;
            const float* hp = HN + t * HPITCH;
            #pragma unroll 4
            for (int i = 0; i < HD; i++)
                acc = fmaf(hp[i], __ldg(wp + i * AD), acc);
            out[(size_t)toks[t] * AD + a] = acc;
        }
        // loop-head sync orders next-tile staging after fc2 reads
    }
}

// ---------------- launch ----------------
extern "C" void kernel_launch(void* const* d_in, const int* in_sizes, int n_in,
                              void* d_out, int out_size)
{
    const float* x    = (const float*)d_in[0];
    const float* hid  = (const float*)d_in[1];
    const float* fc1w = (const float*)d_in[2];
    const float* fc1b = (const float*)d_in[3];
    const float* wih  = (const float*)d_in[4];
    const float* whh  = (const float*)d_in[5];
    const float* bih  = (const float*)d_in[6];
    const float* bhh  = (const float*)d_in[7];
    const float* fc2w = (const float*)d_in[8];
    const float* fc2b = (const float*)d_in[9];
    const float* w1   = (const float*)d_in[10];
    const float* b1   = (const float*)d_in[11];
    const float* w2   = (const float*)d_in[12];
    const float* b2   = (const float*)d_in[13];
    const float* w3   = (const float*)d_in[14];
    const float* b3   = (const float*)d_in[15];
    const float* mk   = (const float*)d_in[16];
    const float* wq   = (const float*)d_in[17];
    const float* bq   = (const float*)d_in[18];
    const float* wk   = (const float*)d_in[19];
    const float* bk   = (const float*)d_in[20];
    const float* unif = (const float*)d_in[21];
    float* out = (float*)d_out;

    cudaFuncSetAttribute(mech_kernel, cudaFuncAttributeMaxDynamicSharedMemorySize, SMEM_BYTES);

    kp_kernel<<<1, 128>>>(mk, wk, bk);
    {
        int tot = NBF1 + NBRZ + NBNQ;
        prep_kernel<<<(tot + 255) / 256, 256>>>(fc1w, wih, whh);
    }
    router_kernel<<<NTOK / 64, 256>>>(hid, w1, b1, w2, b2, w3, b3, wq, bq, unif);
    mech_kernel<<<296, NTHR, SMEM_BYTES>>>(x, hid, fc1b, bih, bhh, fc2w, fc2b, out);
}

// round 14
// speedup vs baseline: 1.0832x; 1.0832x over previous
#include <cuda_runtime.h>
#include <math.h>
#include <stdint.h>

#define NTOK 32768
#define NM   4
#define IND  204
#define HD   128
#define AD   14
#define KD   32
#define TT   32
#define NTHR 256
#define FULL 0xffffffffu

#define PITCH   264
#define XPITCH  212
#define HPITCH  132
#define OFF_XP  8448
#define OFF_TOK 15232
#define SMEM_BYTES ((OFF_TOK + 40) * 4)

// ---------------- device scratch ----------------
__device__ float    g_kp[NM * KD];
__device__ int      g_cnt[NM];
__device__ int      g_ticket;
__device__ int      g_idx[NM * NTOK];
// fc1: [kb][n][8] B-fragment pairs (k,k+4 adjacent)
__device__ __align__(128) uint32_t g_bf1[NM * 26 * 128 * 8];
// r|z packed: [kb][n 0..127][gc 0..3][r0,r1,z0,z1] -> one uint4 per fragment pair
__device__ __align__(128) uint32_t g_brz[NM * 32 * 128 * 16];
// inn|hn: [kb][n 0..255][8] (rows 0-127 = inn/Wi, 128-255 = hn/Whh)
__device__ __align__(128) uint32_t g_bnq[NM * 16 * 256 * 8];

__device__ __forceinline__ float sigmf(float v) { return 1.0f / (1.0f + __expf(-v)); }
__device__ __forceinline__ uint32_t f2tf(float f) {
    uint32_t r; asm("cvt.rna.tf32.f32 %0,%1;" : "=r"(r) : "f"(f)); return r;
}
// non-volatile: lets the compiler schedule loads across mmas
__device__ __forceinline__ void mma8(float c[4], const uint32_t a[4], uint2 b) {
    asm("mma.sync.aligned.m16n8k8.row.col.f32.tf32.tf32.f32 "
        "{%0,%1,%2,%3},{%4,%5,%6,%7},{%8,%9},{%0,%1,%2,%3};"
        : "+f"(c[0]), "+f"(c[1]), "+f"(c[2]), "+f"(c[3])
        : "r"(a[0]), "r"(a[1]), "r"(a[2]), "r"(a[3]), "r"(b.x), "r"(b.y));
}
// pair-interleave offset of column k within a row (A-fragment layout)
__device__ __forceinline__ int pil(int k) {
    return ((k >> 3) << 3) + ((k & 3) << 1) + ((k & 7) >> 2);
}

// ---------------- kernel 0: keys + resets ----------------
__global__ void kp_kernel(const float* __restrict__ mech_keys,
                          const float* __restrict__ wk,
                          const float* __restrict__ bk)
{
    int tid = threadIdx.x;
    if (tid == 0) g_ticket = 0;
    if (tid < NM) g_cnt[tid] = 0;
    if (tid < NM * KD) {
        int m = tid >> 5, k = tid & 31;
        float acc = bk[k];
        #pragma unroll
        for (int i = 0; i < KD; i++)
            acc = fmaf(mech_keys[m * KD + i], wk[i * KD + k], acc);
        g_kp[tid] = acc;
    }
}

// ---------------- prep: pack weights ----------------
#define NBF1 (NM * 26 * 128 * 8)
#define NBRZ (NM * 32 * 128 * 16)
#define NBNQ (NM * 16 * 256 * 8)
__global__ void prep_kernel(const float* __restrict__ fc1w,
                            const float* __restrict__ wih,
                            const float* __restrict__ whh)
{
    int e = blockIdx.x * blockDim.x + threadIdx.x;
    if (e < NBF1) {
        int m = e / 26624, r = e % 26624;
        int kb = r / 1024, r2 = r % 1024;
        int n = r2 >> 3, p = r2 & 7;
        int k = kb * 8 + (p >> 1) + ((p & 1) << 2);
        float v = (k < IND) ? fc1w[((size_t)m * IND + k) * HD + n] : 0.0f;
        g_bf1[e] = f2tf(v);
    } else if (e < NBF1 + NBRZ) {
        int e2 = e - NBF1;
        int m = e2 / 65536, r = e2 % 65536;
        int kb = r / 2048, r2 = r % 2048;
        int n = r2 >> 4, q = r2 & 15;
        int gcp = q >> 2, j = q & 3;
        int p = gcp * 2 + (j & 1);
        int k = kb * 8 + (p >> 1) + ((p & 1) << 2);
        int gate = j >> 1;   // 0 = r, 1 = z
        float v = (k < 128) ? wih[((size_t)m * HD + k) * 384 + gate * 128 + n]
                            : whh[((size_t)m * HD + (k - 128)) * 384 + gate * 128 + n];
        g_brz[e2] = f2tf(v);
    } else if (e < NBF1 + NBRZ + NBNQ) {
        int e3 = e - NBF1 - NBRZ;
        int m = e3 / 32768, r = e3 % 32768;
        int kb = r / 2048, r2 = r % 2048;
        int n = r2 >> 3, p = r2 & 7;
        int k = kb * 8 + (p >> 1) + ((p & 1) << 2);
        int sel = n >> 7, col = n & 127;
        float v = (sel == 0) ? wih[((size_t)m * HD + k) * 384 + 256 + col]
                             : whh[((size_t)m * HD + k) * 384 + 256 + col];
        g_bnq[e3] = f2tf(v);
    }
}

// ---------------- router (proven fp32 path, unchanged) ----------------
__device__ __forceinline__ void layer32(const float* __restrict__ W,
                                        const float* __restrict__ B,
                                        float cur[8], int l, int do_relu)
{
    float nxt[8];
    #pragma unroll
    for (int t = 0; t < 8; t++) nxt[t] = B[l];
    #pragma unroll 4
    for (int i = 0; i < KD; i++) {
        float wv = W[i * KD + l];
        #pragma unroll
        for (int t = 0; t < 8; t++)
            nxt[t] = fmaf(__shfl_sync(FULL, cur[t], i), wv, nxt[t]);
    }
    #pragma unroll
    for (int t = 0; t < 8; t++)
        cur[t] = do_relu ? fmaxf(nxt[t], 0.0f) : nxt[t];
}

__global__ __launch_bounds__(256) void router_kernel(
    const float* __restrict__ hid,
    const float* __restrict__ w1, const float* __restrict__ b1,
    const float* __restrict__ w2, const float* __restrict__ b2,
    const float* __restrict__ w3, const float* __restrict__ b3,
    const float* __restrict__ wq, const float* __restrict__ bq,
    const float* __restrict__ unif)
{
    __shared__ float hs[64 * HD];
    const int tid = threadIdx.x;
    const int t0 = blockIdx.x * 64;
    {
        const float4* src = (const float4*)(hid + (size_t)t0 * HD);
        float4* dst = (float4*)hs;
        for (int e = tid; e < 64 * HD / 4; e += 256) dst[e] = src[e];
    }
    __syncthreads();
    const int w = tid >> 5, l = tid & 31;
    const int wt0 = w * 8;
    float cur[8];
    #pragma unroll
    for (int t = 0; t < 8; t++) cur[t] = b1[l];
    #pragma unroll 4
    for (int i = 0; i < HD; i++) {
        float wv = w1[i * KD + l];
        #pragma unroll
        for (int t = 0; t < 8; t++)
            cur[t] = fmaf(hs[(wt0 + t) * HD + i], wv, cur[t]);
    }
    #pragma unroll
    for (int t = 0; t < 8; t++) cur[t] = fmaxf(cur[t], 0.0f);
    layer32(w2, b2, cur, l, 1);
    layer32(w3, b3, cur, l, 0);
    layer32(wq, bq, cur, l, 0);

    const float scale = 0.17677669529663687f;
    int mysel = 0;
    int mytok = t0 + wt0 + l;
    #pragma unroll
    for (int t = 0; t < 8; t++) {
        float lg[NM];
        #pragma unroll
        for (int m = 0; m < NM; m++) {
            float p = cur[t] * g_kp[m * KD + l];
            #pragma unroll
            for (int off = 16; off > 0; off >>= 1)
                p += __shfl_xor_sync(FULL, p, off);
            lg[m] = p * scale;
        }
        float mx = fmaxf(fmaxf(lg[0], lg[1]), fmaxf(lg[2], lg[3]));
        float es[NM]; float ssum = 0.0f;
        #pragma unroll
        for (int m = 0; m < NM; m++) { es[m] = expf(lg[m] - mx); ssum += es[m]; }
        float inv = 1.0f / ssum;
        int gt = t0 + wt0 + t;
        float best = -1e30f; int sel = 0;
        #pragma unroll
        for (int m = 0; m < NM; m++) {
            float u = unif[gt * NM + m];
            float gmb = -logf(-logf(u + 1e-10f) + 1e-10f);
            float y = es[m] * inv + gmb;
            if (y > best) { best = y; sel = m; }
        }
        if (l == t) mysel = sel;
    }
    #pragma unroll
    for (int m = 0; m < NM; m++) {
        unsigned mask = __ballot_sync(FULL, (l < 8) && (mysel == m));
        if (mask) {
            int leader = __ffs(mask) - 1;
            int base = 0;
            if (l == leader) base = atomicAdd(&g_cnt[m], __popc(mask));
            base = __shfl_sync(FULL, base, leader);
            if ((l < 8) && (mysel == m)) {
                int pos = base + __popc(mask & ((1u << l) - 1));
                g_idx[m * NTOK + pos] = mytok;
            }
        }
    }
}

// ---------------- mech: persistent mma.sync-tf32 fused GRU agent ----------------
__global__ __launch_bounds__(NTHR, 2) void mech_kernel(
    const float* __restrict__ x, const float* __restrict__ hid,
    const float* __restrict__ fc1b,
    const float* __restrict__ bih, const float* __restrict__ bhh,
    const float* __restrict__ fc2w, const float* __restrict__ fc2b,
    float* __restrict__ out)
{
    extern __shared__ float sm[];
    uint32_t* Gp = (uint32_t*)sm;            // [32][264] tf32: 0-127 XA, 128-255 H
    uint32_t* Xp = (uint32_t*)(sm + OFF_XP); // [32][212] tf32 X (dead after fc1)
    float* HN = sm + OFF_XP;                 // [32][132] fp32 hnew (aliases Xp)
    int* toks = (int*)(sm + OFF_TOK);
    int* s_tk = toks + TT;

    const int tid = threadIdx.x;
    const int w = tid >> 5, l = tid & 31;
    const int gr = l >> 2, gc = l & 3;
    const int mb = w >> 2, ng = w & 3;
    float* outH = out + (size_t)NTOK * AD;

    int cc[NM], pre[NM]; int total = 0;
    #pragma unroll
    for (int m = 0; m < NM; m++) {
        cc[m] = g_cnt[m];
        total += (cc[m] + TT - 1) / TT;
        pre[m] = total;
    }

    for (;;) {
        if (tid == 0) *s_tk = atomicAdd(&g_ticket, 1);
        __syncthreads();
        const int tk = *s_tk;
        if (tk >= total) break;
        int m = 0;
        #pragma unroll
        for (int j = 0; j < NM - 1; j++) if (tk >= pre[j]) m = j + 1;
        const int prev = m ? pre[m - 1] : 0;
        const int t0 = (tk - prev) * TT;
        const int nt_tok = min(TT, cc[m] - t0);
        if (tid < TT) toks[tid] = g_idx[m * NTOK + t0 + min(tid, nt_tok - 1)];
        __syncthreads();

        // ---- stage X as tf32 pair-interleaved into Xp ----
        for (int e = tid; e < TT * 52; e += NTHR) {
            int r = e / 52, c4 = e % 52;
            float4 v = make_float4(0.f, 0.f, 0.f, 0.f);
            if (c4 < 51) v = ((const float4*)(x + (size_t)toks[r] * IND))[c4];
            int k0 = c4 * 4;
            uint32_t* dst = Xp + r * XPITCH + ((k0 >> 3) << 3) + ((k0 & 7) >> 2);
            dst[0] = f2tf(v.x); dst[2] = f2tf(v.y); dst[4] = f2tf(v.z); dst[6] = f2tf(v.w);
        }
        // ---- stage H as tf32 pair-interleaved into Gp cols 128.. ----
        for (int e = tid; e < TT * 32; e += NTHR) {
            int r = e >> 5, c4 = e & 31;
            float4 v = ((const float4*)(hid + (size_t)toks[r] * HD))[c4];
            int k0 = 128 + c4 * 4;
            uint32_t* dst = Gp + r * PITCH + ((k0 >> 3) << 3) + ((k0 & 7) >> 2);
            dst[0] = f2tf(v.x); dst[2] = f2tf(v.y); dst[4] = f2tf(v.z); dst[6] = f2tf(v.w);
        }
        __syncthreads();

        // ---- fc1: 8 warps, warp = m16 x n32 ----
        {
            float c[4][4];
            #pragma unroll
            for (int nt = 0; nt < 4; nt++) {
                int col = ng * 32 + nt * 8 + gc * 2;
                float b0 = __ldg(fc1b + m * HD + col);
                float b1 = __ldg(fc1b + m * HD + col + 1);
                c[nt][0] = b0; c[nt][1] = b1;
                c[nt][2] = b0; c[nt][3] = b1;
            }
            const uint32_t* Bf = g_bf1 + m * 26624 + (ng * 32 + gr) * 8 + gc * 2;
            const uint32_t* Ax0 = Xp + (mb * 16 + gr) * XPITCH + gc * 2;
            const uint32_t* Ax1 = Ax0 + 8 * XPITCH;
            #pragma unroll 2
            for (int kb = 0; kb < 26; kb++) {
                uint32_t a[4];
                {
                    uint2 lo = *(const uint2*)(Ax0 + kb * 8);
                    uint2 hi = *(const uint2*)(Ax1 + kb * 8);
                    a[0] = lo.x; a[1] = hi.x; a[2] = lo.y; a[3] = hi.y;
                }
                uint2 b[4];
                #pragma unroll
                for (int nt = 0; nt < 4; nt++)
                    b[nt] = __ldg((const uint2*)(Bf + kb * 1024 + nt * 64));
                #pragma unroll
                for (int nt = 0; nt < 4; nt++)
                    mma8(c[nt], a, b[nt]);
            }
            #pragma unroll
            for (int nt = 0; nt < 4; nt++) {
                int row = mb * 16 + gr;
                int col = ng * 32 + nt * 8 + gc * 2;
                int p = pil(col);
                Gp[row * PITCH + p]           = f2tf(fmaxf(c[nt][0], 0.f));
                Gp[row * PITCH + p + 2]       = f2tf(fmaxf(c[nt][1], 0.f));
                Gp[(row + 8) * PITCH + p]     = f2tf(fmaxf(c[nt][2], 0.f));
                Gp[(row + 8) * PITCH + p + 2] = f2tf(fmaxf(c[nt][3], 0.f));
            }
        }
        __syncthreads();

        // ---- gates (2 merged A-passes, packed rz loads) + in-register GRU ----
        {
            const int rowb = mb * 16;
            const uint32_t* Brz2 = g_brz + m * 65536 + (ng * 32 + gr) * 16 + gc * 4;
            const uint32_t* Bnqp = g_bnq + m * 32768 + (ng * 32 + gr) * 8 + gc * 2;
            const uint32_t* Ag0 = Gp + (rowb + gr) * PITCH + gc * 2;
            const uint32_t* Ag1 = Ag0 + 8 * PITCH;
            float cr[4][4], cz[4][4], cn[4][4], cq[4][4];
            #pragma unroll
            for (int nt = 0; nt < 4; nt++) {
                int col = ng * 32 + nt * 8 + gc * 2;
                float r0 = __ldg(bih + m * 384 + col) + __ldg(bhh + m * 384 + col);
                float r1 = __ldg(bih + m * 384 + col + 1) + __ldg(bhh + m * 384 + col + 1);
                float z0 = __ldg(bih + m * 384 + 128 + col) + __ldg(bhh + m * 384 + 128 + col);
                float z1 = __ldg(bih + m * 384 + 128 + col + 1) + __ldg(bhh + m * 384 + 128 + col + 1);
                float n0 = __ldg(bih + m * 384 + 256 + col);
                float n1 = __ldg(bih + m * 384 + 256 + col + 1);
                float q0 = __ldg(bhh + m * 384 + 256 + col);
                float q1 = __ldg(bhh + m * 384 + 256 + col + 1);
                cr[nt][0] = r0; cr[nt][1] = r1; cr[nt][2] = r0; cr[nt][3] = r1;
                cz[nt][0] = z0; cz[nt][1] = z1; cz[nt][2] = z0; cz[nt][3] = z1;
                cn[nt][0] = n0; cn[nt][1] = n1; cn[nt][2] = n0; cn[nt][3] = n1;
                cq[nt][0] = q0; cq[nt][1] = q1; cq[nt][2] = q0; cq[nt][3] = q1;
            }
            // pass 1: kb 0..15 (XA half) -> r, z, inn
            #pragma unroll 2
            for (int kb = 0; kb < 16; kb++) {
                uint32_t a[4];
                uint2 lo = *(const uint2*)(Ag0 + kb * 8);
                uint2 hi = *(const uint2*)(Ag1 + kb * 8);
                a[0] = lo.x; a[1] = hi.x; a[2] = lo.y; a[3] = hi.y;
                uint4 brz4[4]; uint2 bn2[4];
                #pragma unroll
                for (int nt = 0; nt < 4; nt++)
                    brz4[nt] = __ldg((const uint4*)(Brz2 + kb * 2048 + nt * 128));
                #pragma unroll
                for (int nt = 0; nt < 4; nt++)
                    bn2[nt] = __ldg((const uint2*)(Bnqp + kb * 2048 + nt * 64));
                #pragma unroll
                for (int nt = 0; nt < 4; nt++) {
                    mma8(cr[nt], a, make_uint2(brz4[nt].x, brz4[nt].y));
                    mma8(cz[nt], a, make_uint2(brz4[nt].z, brz4[nt].w));
                    mma8(cn[nt], a, bn2[nt]);
                }
            }
            // pass 2: kb 16..31 (H half) -> r, z, hn
            #pragma unroll 2
            for (int kb = 16; kb < 32; kb++) {
                uint32_t a[4];
                uint2 lo = *(const uint2*)(Ag0 + kb * 8);
                uint2 hi = *(const uint2*)(Ag1 + kb * 8);
                a[0] = lo.x; a[1] = hi.x; a[2] = lo.y; a[3] = hi.y;
                uint4 brz4[4]; uint2 bq2[4];
                #pragma unroll
                for (int nt = 0; nt < 4; nt++)
                    brz4[nt] = __ldg((const uint4*)(Brz2 + kb * 2048 + nt * 128));
                #pragma unroll
                for (int nt = 0; nt < 4; nt++)
                    bq2[nt] = __ldg((const uint2*)(Bnqp + (kb - 16) * 2048 + 1024 + nt * 64));
                #pragma unroll
                for (int nt = 0; nt < 4; nt++) {
                    mma8(cr[nt], a, make_uint2(brz4[nt].x, brz4[nt].y));
                    mma8(cz[nt], a, make_uint2(brz4[nt].z, brz4[nt].w));
                    mma8(cq[nt], a, bq2[nt]);
                }
            }
            // in-register GRU epilogue (h from global fp32)
            #pragma unroll
            for (int nt = 0; nt < 4; nt++) {
                int colb = ng * 32 + nt * 8 + gc * 2;
                #pragma unroll
                for (int idx = 0; idx < 4; idx++) {
                    int row = rowb + gr + ((idx >> 1) << 3);
                    int col = colb + (idx & 1);
                    float rv = sigmf(cr[nt][idx]);
                    float zv = sigmf(cz[nt][idx]);
                    float gg = tanhf(cn[nt][idx] + rv * cq[nt][idx]);
                    float hv = __ldg(hid + (size_t)toks[row] * HD + col);
                    float h2 = (1.0f - zv) * gg + zv * hv;
                    HN[row * HPITCH + col] = h2;
                    outH[(size_t)toks[row] * HD + col] = h2;
                }
            }
        }
        __syncthreads();

        // ---- fc2 over hnew (HN plain fp32) ----
        for (int oi = tid; oi < TT * AD; oi += NTHR) {
            int t = oi / AD, a = oi - t * AD;
            float acc = fc2b[m * AD + a];
            const float* wp = fc2w + m * HD * AD + a;
            const float* hp = HN + t * HPITCH;
            #pragma unroll 4
            for (int i = 0; i < HD; i++)
                acc = fmaf(hp[i], __ldg(wp + i * AD), acc);
            out[(size_t)toks[t] * AD + a] = acc;
        }
        // loop-head sync orders next-tile staging after fc2 reads
    }
}

// ---------------- launch ----------------
extern "C" void kernel_launch(void* const* d_in, const int* in_sizes, int n_in,
                              void* d_out, int out_size)
{
    const float* x    = (const float*)d_in[0];
    const float* hid  = (const float*)d_in[1];
    const float* fc1w = (const float*)d_in[2];
    const float* fc1b = (const float*)d_in[3];
    const float* wih  = (const float*)d_in[4];
    const float* whh  = (const float*)d_in[5];
    const float* bih  = (const float*)d_in[6];
    const float* bhh  = (const float*)d_in[7];
    const float* fc2w = (const float*)d_in[8];
    const float* fc2b = (const float*)d_in[9];
    const float* w1   = (const float*)d_in[10];
    const float* b1   = (const float*)d_in[11];
    const float* w2   = (const float*)d_in[12];
    const float* b2   = (const float*)d_in[13];
    const float* w3   = (const float*)d_in[14];
    const float* b3   = (const float*)d_in[15];
    const float* mk   = (const float*)d_in[16];
    const float* wq   = (const float*)d_in[17];
    const float* bq   = (const float*)d_in[18];
    const float* wk   = (const float*)d_in[19];
    const float* bk   = (const float*)d_in[20];
    const float* unif = (const float*)d_in[21];
    float* out = (float*)d_out;

    cudaFuncSetAttribute(mech_kernel, cudaFuncAttributeMaxDynamicSharedMemorySize, SMEM_BYTES);

    kp_kernel<<<1, 128>>>(mk, wk, bk);
    {
        int tot = NBF1 + NBRZ + NBNQ;
        prep_kernel<<<(tot + 255) / 256, 256>>>(fc1w, wih, whh);
    }
    router_kernel<<<NTOK / 64, 256>>>(hid, w1, b1, w2, b2, w3, b3, wq, bq, unif);
    mech_kernel<<<296, NTHR, SMEM_BYTES>>>(x, hid, fc1b, bih, bhh, fc2w, fc2b, out);
}

// round 16
// speedup vs baseline: 1.2944x; 1.1949x over previous
#include <cuda_runtime.h>
#include <cuda_fp16.h>
#include <math.h>
#include <stdint.h>

#define NTOK 32768
#define NM   4
#define IND  204
#define HD   128
#define AD   14
#define KD   32
#define TT   32
#define NTHR 256
#define FULL 0xffffffffu

#define GPITCH  132     // uint32 pitch, conflict-free 8-row pattern
#define XPITCH  108
#define HNP     132
#define OFF_XP  4224
#define OFF_HN  7680
#define OFF_TOK 11904
#define SMEM_BYTES ((OFF_TOK + 40) * 4)

// ---------------- device scratch ----------------
__device__ float    g_kp[NM * KD];
__device__ int      g_cnt[NM];
__device__ int      g_ticket;
__device__ int      g_idx[NM * NTOK];
// fp16 B-fragment images. Each uint32 = half2 (k, k+1); pair-interleaved so a
// uint2 at gc*2 yields k-pairs (2gc,2gc+1) and (2gc+8,2gc+9) of a k16 block.
__device__ __align__(128) uint32_t g_bf1[NM * 13 * 128 * 8];    // fc1: K=208(pad), N=128
__device__ __align__(128) uint32_t g_brz[NM * 16 * 128 * 16];   // r|z: K=256, uint4 {r0,r1,z0,z1}
__device__ __align__(128) uint32_t g_bnq[NM * 8 * 256 * 8];     // inn|hn: K=128, n 0-127 inn / 128-255 hn

__device__ __forceinline__ float sigmf(float v) { return 1.0f / (1.0f + __expf(-v)); }
__device__ __forceinline__ uint32_t pkh2(float a, float b) {
    __half2 h = __floats2half2_rn(a, b);
    return *reinterpret_cast<uint32_t*>(&h);
}
// fp16 mma, k16, fp32 accumulate. Non-volatile for scheduling freedom.
__device__ __forceinline__ void mma16(float c[4], const uint32_t a[4], uint2 b) {
    asm("mma.sync.aligned.m16n8k16.row.col.f32.f16.f16.f32 "
        "{%0,%1,%2,%3},{%4,%5,%6,%7},{%8,%9},{%0,%1,%2,%3};"
        : "+f"(c[0]), "+f"(c[1]), "+f"(c[2]), "+f"(c[3])
        : "r"(a[0]), "r"(a[1]), "r"(a[2]), "r"(a[3]), "r"(b.x), "r"(b.y));
}
// pair-interleave position of k-pair index j within a k16 block (8 pairs)
__device__ __forceinline__ int pilj(int j) { return ((j & 3) << 1) + (j >> 2); }

// ---------------- kernel 0: keys + resets ----------------
__global__ void kp_kernel(const float* __restrict__ mech_keys,
                          const float* __restrict__ wk,
                          const float* __restrict__ bk)
{
    int tid = threadIdx.x;
    if (tid == 0) g_ticket = 0;
    if (tid < NM) g_cnt[tid] = 0;
    if (tid < NM * KD) {
        int m = tid >> 5, k = tid & 31;
        float acc = bk[k];
        #pragma unroll
        for (int i = 0; i < KD; i++)
            acc = fmaf(mech_keys[m * KD + i], wk[i * KD + k], acc);
        g_kp[tid] = acc;
    }
}

// ---------------- prep: pack fp16 weight images ----------------
#define NBF1 (NM * 13 * 128 * 8)
#define NBRZ (NM * 16 * 128 * 16)
#define NBNQ (NM * 8 * 256 * 8)
__global__ void prep_kernel(const float* __restrict__ fc1w,
                            const float* __restrict__ wih,
                            const float* __restrict__ whh)
{
    int e = blockIdx.x * blockDim.x + threadIdx.x;
    if (e < NBF1) {
        int m = e / 13312, r = e % 13312;
        int kb = r / 1024, r2 = r % 1024;
        int n = r2 >> 3, p = r2 & 7;
        int j = (p >> 1) + ((p & 1) << 2);
        int k0 = kb * 16 + 2 * j;
        float lo = (k0 < IND)     ? fc1w[((size_t)m * IND + k0) * HD + n]     : 0.0f;
        float hi = (k0 + 1 < IND) ? fc1w[((size_t)m * IND + k0 + 1) * HD + n] : 0.0f;
        g_bf1[e] = pkh2(lo, hi);
    } else if (e < NBF1 + NBRZ) {
        int e2 = e - NBF1;
        int m = e2 / 32768, r = e2 % 32768;
        int kb = r / 2048, r2 = r % 2048;
        int n = r2 >> 4, q = r2 & 15;
        int gcp = q >> 2, s = q & 3;
        int j = gcp + ((s & 1) << 2);
        int k0 = kb * 16 + 2 * j;
        int gate = s >> 1;   // 0 = r, 1 = z
        float lo = (k0 < 128) ? wih[((size_t)m * HD + k0) * 384 + gate * 128 + n]
                              : whh[((size_t)m * HD + (k0 - 128)) * 384 + gate * 128 + n];
        float hi = (k0 + 1 < 128) ? wih[((size_t)m * HD + k0 + 1) * 384 + gate * 128 + n]
                                  : whh[((size_t)m * HD + (k0 + 1 - 128)) * 384 + gate * 128 + n];
        g_brz[e2] = pkh2(lo, hi);
    } else if (e < NBF1 + NBRZ + NBNQ) {
        int e3 = e - NBF1 - NBRZ;
        int m = e3 / 16384, r = e3 % 16384;
        int kb = r / 2048, r2 = r % 2048;
        int n = r2 >> 3, p = r2 & 7;
        int j = (p >> 1) + ((p & 1) << 2);
        int k0 = kb * 16 + 2 * j;
        int sel = n >> 7, col = n & 127;
        const float* src = sel ? whh : wih;
        float lo = src[((size_t)m * HD + k0) * 384 + 256 + col];
        float hi = src[((size_t)m * HD + k0 + 1) * 384 + 256 + col];
        g_bnq[e3] = pkh2(lo, hi);
    }
}

// ---------------- router (proven fp32 path, unchanged) ----------------
__device__ __forceinline__ void layer32(const float* __restrict__ W,
                                        const float* __restrict__ B,
                                        float cur[8], int l, int do_relu)
{
    float nxt[8];
    #pragma unroll
    for (int t = 0; t < 8; t++) nxt[t] = B[l];
    #pragma unroll 4
    for (int i = 0; i < KD; i++) {
        float wv = W[i * KD + l];
        #pragma unroll
        for (int t = 0; t < 8; t++)
            nxt[t] = fmaf(__shfl_sync(FULL, cur[t], i), wv, nxt[t]);
    }
    #pragma unroll
    for (int t = 0; t < 8; t++)
        cur[t] = do_relu ? fmaxf(nxt[t], 0.0f) : nxt[t];
}

__global__ __launch_bounds__(256) void router_kernel(
    const float* __restrict__ hid,
    const float* __restrict__ w1, const float* __restrict__ b1,
    const float* __restrict__ w2, const float* __restrict__ b2,
    const float* __restrict__ w3, const float* __restrict__ b3,
    const float* __restrict__ wq, const float* __restrict__ bq,
    const float* __restrict__ unif)
{
    __shared__ float hs[64 * HD];
    const int tid = threadIdx.x;
    const int t0 = blockIdx.x * 64;
    {
        const float4* src = (const float4*)(hid + (size_t)t0 * HD);
        float4* dst = (float4*)hs;
        for (int e = tid; e < 64 * HD / 4; e += 256) dst[e] = src[e];
    }
    __syncthreads();
    const int w = tid >> 5, l = tid & 31;
    const int wt0 = w * 8;
    float cur[8];
    #pragma unroll
    for (int t = 0; t < 8; t++) cur[t] = b1[l];
    #pragma unroll 4
    for (int i = 0; i < HD; i++) {
        float wv = w1[i * KD + l];
        #pragma unroll
        for (int t = 0; t < 8; t++)
            cur[t] = fmaf(hs[(wt0 + t) * HD + i], wv, cur[t]);
    }
    #pragma unroll
    for (int t = 0; t < 8; t++) cur[t] = fmaxf(cur[t], 0.0f);
    layer32(w2, b2, cur, l, 1);
    layer32(w3, b3, cur, l, 0);
    layer32(wq, bq, cur, l, 0);

    const float scale = 0.17677669529663687f;
    int mysel = 0;
    int mytok = t0 + wt0 + l;
    #pragma unroll
    for (int t = 0; t < 8; t++) {
        float lg[NM];
        #pragma unroll
        for (int m = 0; m < NM; m++) {
            float p = cur[t] * g_kp[m * KD + l];
            #pragma unroll
            for (int off = 16; off > 0; off >>= 1)
                p += __shfl_xor_sync(FULL, p, off);
            lg[m] = p * scale;
        }
        float mx = fmaxf(fmaxf(lg[0], lg[1]), fmaxf(lg[2], lg[3]));
        float es[NM]; float ssum = 0.0f;
        #pragma unroll
        for (int m = 0; m < NM; m++) { es[m] = expf(lg[m] - mx); ssum += es[m]; }
        float inv = 1.0f / ssum;
        int gt = t0 + wt0 + t;
        float best = -1e30f; int sel = 0;
        #pragma unroll
        for (int m = 0; m < NM; m++) {
            float u = unif[gt * NM + m];
            float gmb = -logf(-logf(u + 1e-10f) + 1e-10f);
            float y = es[m] * inv + gmb;
            if (y > best) { best = y; sel = m; }
        }
        if (l == t) mysel = sel;
    }
    #pragma unroll
    for (int m = 0; m < NM; m++) {
        unsigned mask = __ballot_sync(FULL, (l < 8) && (mysel == m));
        if (mask) {
            int leader = __ffs(mask) - 1;
            int base = 0;
            if (l == leader) base = atomicAdd(&g_cnt[m], __popc(mask));
            base = __shfl_sync(FULL, base, leader);
            if ((l < 8) && (mysel == m)) {
                int pos = base + __popc(mask & ((1u << l) - 1));
                g_idx[m * NTOK + pos] = mytok;
            }
        }
    }
}

// ---------------- mech: persistent mma.sync-fp16 fused GRU agent ----------------
__global__ __launch_bounds__(NTHR, 2) void mech_kernel(
    const float* __restrict__ x, const float* __restrict__ hid,
    const float* __restrict__ fc1b,
    const float* __restrict__ bih, const float* __restrict__ bhh,
    const float* __restrict__ fc2w, const float* __restrict__ fc2b,
    float* __restrict__ out)
{
    extern __shared__ float sm[];
    uint32_t* Gp = (uint32_t*)sm;            // [32][132] half2: cols 0-63 XA, 64-127 H
    uint32_t* Xp = (uint32_t*)(sm + OFF_XP); // [32][108] half2 X (dead after fc1)
    float* HN = sm + OFF_HN;                 // [32][132] fp32 hnew
    int* toks = (int*)(sm + OFF_TOK);
    int* s_tk = toks + TT;

    const int tid = threadIdx.x;
    const int w = tid >> 5, l = tid & 31;
    const int gr = l >> 2, gc = l & 3;
    const int mb = w >> 2, ng = w & 3;
    float* outH = out + (size_t)NTOK * AD;

    int cc[NM], pre[NM]; int total = 0;
    #pragma unroll
    for (int m = 0; m < NM; m++) {
        cc[m] = g_cnt[m];
        total += (cc[m] + TT - 1) / TT;
        pre[m] = total;
    }

    for (;;) {
        if (tid == 0) *s_tk = atomicAdd(&g_ticket, 1);
        __syncthreads();
        const int tk = *s_tk;
        if (tk >= total) break;
        int m = 0;
        #pragma unroll
        for (int j = 0; j < NM - 1; j++) if (tk >= pre[j]) m = j + 1;
        const int prev = m ? pre[m - 1] : 0;
        const int t0 = (tk - prev) * TT;
        const int nt_tok = min(TT, cc[m] - t0);
        if (tid < TT) toks[tid] = g_idx[m * NTOK + t0 + min(tid, nt_tok - 1)];
        __syncthreads();

        // ---- stage X as fp16 pairs (pair-interleaved per k16 block) ----
        for (int e = tid; e < TT * 52; e += NTHR) {
            int r = e / 52, c4 = e % 52;
            float4 v = make_float4(0.f, 0.f, 0.f, 0.f);
            if (c4 < 51) v = ((const float4*)(x + (size_t)toks[r] * IND))[c4];
            int j0 = 2 * c4;                  // k-pair indices j0, j0+1 (same k16 block)
            int kb = j0 >> 3;
            uint32_t* dst = Xp + r * XPITCH + kb * 8;
            dst[pilj(j0 & 7)]       = pkh2(v.x, v.y);
            dst[pilj((j0 + 1) & 7)] = pkh2(v.z, v.w);
        }
        // ---- stage H into Gp cols 64.. ----
        for (int e = tid; e < TT * 32; e += NTHR) {
            int r = e >> 5, c4 = e & 31;
            float4 v = ((const float4*)(hid + (size_t)toks[r] * HD))[c4];
            int j0 = 2 * c4;
            int kb = j0 >> 3;
            uint32_t* dst = Gp + r * GPITCH + 64 + kb * 8;
            dst[pilj(j0 & 7)]       = pkh2(v.x, v.y);
            dst[pilj((j0 + 1) & 7)] = pkh2(v.z, v.w);
        }
        __syncthreads();

        // ---- fc1: 8 warps, warp = m16 x n32, 13 k16 steps ----
        {
            float c[4][4];
            #pragma unroll
            for (int nt = 0; nt < 4; nt++) {
                int col = ng * 32 + nt * 8 + gc * 2;
                float b0 = __ldg(fc1b + m * HD + col);
                float b1 = __ldg(fc1b + m * HD + col + 1);
                c[nt][0] = b0; c[nt][1] = b1;
                c[nt][2] = b0; c[nt][3] = b1;
            }
            const uint32_t* Bf = g_bf1 + m * 13312 + (ng * 32 + gr) * 8 + gc * 2;
            const uint32_t* Ax0 = Xp + (mb * 16 + gr) * XPITCH + gc * 2;
            const uint32_t* Ax1 = Ax0 + 8 * XPITCH;
            #pragma unroll 2
            for (int kb = 0; kb < 13; kb++) {
                uint32_t a[4];
                {
                    uint2 lo = *(const uint2*)(Ax0 + kb * 8);
                    uint2 hi = *(const uint2*)(Ax1 + kb * 8);
                    a[0] = lo.x; a[1] = hi.x; a[2] = lo.y; a[3] = hi.y;
                }
                uint2 b[4];
                #pragma unroll
                for (int nt = 0; nt < 4; nt++)
                    b[nt] = __ldg((const uint2*)(Bf + kb * 1024 + nt * 64));
                #pragma unroll
                for (int nt = 0; nt < 4; nt++)
                    mma16(c[nt], a, b[nt]);
            }
            // relu + pack to Gp cols 0-63 (XA), pair-interleaved
            #pragma unroll
            for (int nt = 0; nt < 4; nt++) {
                int row = mb * 16 + gr;
                int j = ng * 16 + nt * 4 + gc;     // k-pair index of cols (2j, 2j+1)
                int pos = (j >> 3) * 8 + pilj(j & 7);
                Gp[row * GPITCH + pos]       = pkh2(fmaxf(c[nt][0], 0.f), fmaxf(c[nt][1], 0.f));
                Gp[(row + 8) * GPITCH + pos] = pkh2(fmaxf(c[nt][2], 0.f), fmaxf(c[nt][3], 0.f));
            }
        }
        __syncthreads();

        // ---- gates (2 merged k16 passes) + in-register GRU ----
        {
            const int rowb = mb * 16;
            const uint32_t* Brz2 = g_brz + m * 32768 + (ng * 32 + gr) * 16 + gc * 4;
            const uint32_t* Bnqp = g_bnq + m * 16384 + (ng * 32 + gr) * 8 + gc * 2;
            const uint32_t* Ag0 = Gp + (rowb + gr) * GPITCH + gc * 2;
            const uint32_t* Ag1 = Ag0 + 8 * GPITCH;
            float cr[4][4], cz[4][4], cn[4][4], cq[4][4];
            #pragma unroll
            for (int nt = 0; nt < 4; nt++) {
                int col = ng * 32 + nt * 8 + gc * 2;
                float r0 = __ldg(bih + m * 384 + col) + __ldg(bhh + m * 384 + col);
                float r1 = __ldg(bih + m * 384 + col + 1) + __ldg(bhh + m * 384 + col + 1);
                float z0 = __ldg(bih + m * 384 + 128 + col) + __ldg(bhh + m * 384 + 128 + col);
                float z1 = __ldg(bih + m * 384 + 128 + col + 1) + __ldg(bhh + m * 384 + 128 + col + 1);
                float n0 = __ldg(bih + m * 384 + 256 + col);
                float n1 = __ldg(bih + m * 384 + 256 + col + 1);
                float q0 = __ldg(bhh + m * 384 + 256 + col);
                float q1 = __ldg(bhh + m * 384 + 256 + col + 1);
                cr[nt][0] = r0; cr[nt][1] = r1; cr[nt][2] = r0; cr[nt][3] = r1;
                cz[nt][0] = z0; cz[nt][1] = z1; cz[nt][2] = z0; cz[nt][3] = z1;
                cn[nt][0] = n0; cn[nt][1] = n1; cn[nt][2] = n0; cn[nt][3] = n1;
                cq[nt][0] = q0; cq[nt][1] = q1; cq[nt][2] = q0; cq[nt][3] = q1;
            }
            // pass 1: kb 0..7 (XA half, Gp cols 0-63) -> r, z, inn
            #pragma unroll 2
            for (int kb = 0; kb < 8; kb++) {
                uint32_t a[4];
                uint2 lo = *(const uint2*)(Ag0 + kb * 8);
                uint2 hi = *(const uint2*)(Ag1 + kb * 8);
                a[0] = lo.x; a[1] = hi.x; a[2] = lo.y; a[3] = hi.y;
                uint4 brz4[4]; uint2 bn2[4];
                #pragma unroll
                for (int nt = 0; nt < 4; nt++)
                    brz4[nt] = __ldg((const uint4*)(Brz2 + kb * 2048 + nt * 128));
                #pragma unroll
                for (int nt = 0; nt < 4; nt++)
                    bn2[nt] = __ldg((const uint2*)(Bnqp + kb * 2048 + nt * 64));
                #pragma unroll
                for (int nt = 0; nt < 4; nt++) {
                    mma16(cr[nt], a, make_uint2(brz4[nt].x, brz4[nt].y));
                    mma16(cz[nt], a, make_uint2(brz4[nt].z, brz4[nt].w));
                    mma16(cn[nt], a, bn2[nt]);
                }
            }
            // pass 2: kb 8..15 (H half, Gp cols 64-127) -> r, z, hn
            #pragma unroll 2
            for (int kb = 8; kb < 16; kb++) {
                uint32_t a[4];
                uint2 lo = *(const uint2*)(Ag0 + kb * 8);
                uint2 hi = *(const uint2*)(Ag1 + kb * 8);
                a[0] = lo.x; a[1] = hi.x; a[2] = lo.y; a[3] = hi.y;
                uint4 brz4[4]; uint2 bq2[4];
                #pragma unroll
                for (int nt = 0; nt < 4; nt++)
                    brz4[nt] = __ldg((const uint4*)(Brz2 + kb * 2048 + nt * 128));
                #pragma unroll
                for (int nt = 0; nt < 4; nt++)
                    bq2[nt] = __ldg((const uint2*)(Bnqp + (kb - 8) * 2048 + 1024 + nt * 64));
                #pragma unroll
                for (int nt = 0; nt < 4; nt++) {
                    mma16(cr[nt], a, make_uint2(brz4[nt].x, brz4[nt].y));
                    mma16(cz[nt], a, make_uint2(brz4[nt].z, brz4[nt].w));
                    mma16(cq[nt], a, bq2[nt]);
                }
            }
            // in-register GRU epilogue (h from global fp32)
            #pragma unroll
            for (int nt = 0; nt < 4; nt++) {
                int colb = ng * 32 + nt * 8 + gc * 2;
                #pragma unroll
                for (int idx = 0; idx < 4; idx++) {
                    int row = rowb + gr + ((idx >> 1) << 3);
                    int col = colb + (idx & 1);
                    float rv = sigmf(cr[nt][idx]);
                    float zv = sigmf(cz[nt][idx]);
                    float gg = tanhf(cn[nt][idx] + rv * cq[nt][idx]);
                    float hv = __ldg(hid + (size_t)toks[row] * HD + col);
                    float h2 = (1.0f - zv) * gg + zv * hv;
                    HN[row * HNP + col] = h2;
                    outH[(size_t)toks[row] * HD + col] = h2;
                }
            }
        }
        __syncthreads();

        // ---- fc2 over hnew (HN plain fp32) ----
        for (int oi = tid; oi < TT * AD; oi += NTHR) {
            int t = oi / AD, a = oi - t * AD;
            float acc = fc2b[m * AD + a];
            const float* wp = fc2w + m * HD * AD + a;
            const float* hp = HN + t * HNP;
            #pragma unroll 4
            for (int i = 0; i < HD; i++)
                acc = fmaf(hp[i], __ldg(wp + i * AD), acc);
            out[(size_t)toks[t] * AD + a] = acc;
        }
        // loop-head sync orders next-tile staging after fc2 reads
    }
}

// ---------------- launch ----------------
extern "C" void kernel_launch(void* const* d_in, const int* in_sizes, int n_in,
                              void* d_out, int out_size)
{
    const float* x    = (const float*)d_in[0];
    const float* hid  = (const float*)d_in[1];
    const float* fc1w = (const float*)d_in[2];
    const float* fc1b = (const float*)d_in[3];
    const float* wih  = (const float*)d_in[4];
    const float* whh  = (const float*)d_in[5];
    const float* bih  = (const float*)d_in[6];
    const float* bhh  = (const float*)d_in[7];
    const float* fc2w = (const float*)d_in[8];
    const float* fc2b = (const float*)d_in[9];
    const float* w1   = (const float*)d_in[10];
    const float* b1   = (const float*)d_in[11];
    const float* w2   = (const float*)d_in[12];
    const float* b2   = (const float*)d_in[13];
    const float* w3   = (const float*)d_in[14];
    const float* b3   = (const float*)d_in[15];
    const float* mk   = (const float*)d_in[16];
    const float* wq   = (const float*)d_in[17];
    const float* bq   = (const float*)d_in[18];
    const float* wk   = (const float*)d_in[19];
    const float* bk   = (const float*)d_in[20];
    const float* unif = (const float*)d_in[21];
    float* out = (float*)d_out;

    cudaFuncSetAttribute(mech_kernel, cudaFuncAttributeMaxDynamicSharedMemorySize, SMEM_BYTES);

    kp_kernel<<<1, 128>>>(mk, wk, bk);
    {
        int tot = NBF1 + NBRZ + NBNQ;
        prep_kernel<<<(tot + 255) / 256, 256>>>(fc1w, wih, whh);
    }
    router_kernel<<<NTOK / 64, 256>>>(hid, w1, b1, w2, b2, w3, b3, wq, bq, unif);
    mech_kernel<<<296, NTHR, SMEM_BYTES>>>(x, hid, fc1b, bih, bhh, fc2w, fc2b, out);
}